// round 7
// baseline (speedup 1.0000x reference)
#include <cuda_runtime.h>
#include <cstdint>

// Problem constants
#define BB   64
#define MM   50176         // B*28*28
#define NN   768
#define KK   192
#define KWRD 48            // K in int words (4 int8 each)

// ---------------- device scratch ----------------
__device__ unsigned g_amax_x, g_amax_w;
__device__ int4 g_xq[MM * KWRD / 4];    // [M][48] words: A, row-major k
__device__ int4 g_wq[NN * KWRD / 4];    // [N][48] words: B, n-major (natural w layout)

// ---------------- small kernels ----------------
__global__ void k_init() { g_amax_x = 0u; g_amax_w = 0u; }

__global__ void k_absmax(const float4* __restrict__ px, int nx4,
                         const float4* __restrict__ pw, int nw4) {
    const float4* p = blockIdx.y ? pw : px;
    const int n4 = blockIdx.y ? nw4 : nx4;
    float m = 0.f;
    for (int i = blockIdx.x * blockDim.x + threadIdx.x; i < n4; i += gridDim.x * blockDim.x) {
        float4 v = p[i];
        m = fmaxf(m, fmaxf(fmaxf(fabsf(v.x), fabsf(v.y)), fmaxf(fabsf(v.z), fabsf(v.w))));
    }
    #pragma unroll
    for (int o = 16; o; o >>= 1) m = fmaxf(m, __shfl_xor_sync(0xffffffffu, m, o));
    __shared__ float sm[8];
    if ((threadIdx.x & 31) == 0) sm[threadIdx.x >> 5] = m;
    __syncthreads();
    if (threadIdx.x < 32) {
        m = (threadIdx.x < 8) ? sm[threadIdx.x] : 0.f;
        #pragma unroll
        for (int o = 4; o; o >>= 1) m = fmaxf(m, __shfl_xor_sync(0xffffffffu, m, o));
        if (threadIdx.x == 0)
            atomicMax(blockIdx.y ? &g_amax_w : &g_amax_x, __float_as_uint(m));
    }
}

__device__ __forceinline__ int quant1(float v, float s) {
    float t = v / s;
    t = fminf(fmaxf(t, -127.f), 127.f);
    return __float2int_rn(t);
}
__device__ __forceinline__ int pack4(float4 v, float s) {
    int i0 = quant1(v.x, s), i1 = quant1(v.y, s), i2 = quant1(v.z, s), i3 = quant1(v.w, s);
    return (i0 & 0xff) | ((i1 & 0xff) << 8) | ((i2 & 0xff) << 16) | ((i3 & 0xff) << 24);
}

// Fused quantization: blocks [0,1792) handle x slabs, [1792,1936) handle w.
__global__ void __launch_bounds__(256) k_quant(const float* __restrict__ x,
                                               const float* __restrict__ w) {
    const int t = threadIdx.x;
    if (blockIdx.x < 1792) {
        __shared__ int sq[28 * 49];
        const int b = blockIdx.x / 28, gx = blockIdx.x % 28;
        const float s = fmaxf(__uint_as_float(g_amax_x), 1e-8f) / 127.f;
        for (int i = t; i < 1344; i += 256) {
            int row = i / 56, pos = i - row * 56;        // row = c*8+pr
            int c = row >> 3, pr = row & 7;
            float4 v = *(const float4*)(x + (((b * 3 + c) * 224 + gx * 8 + pr) * 224) + pos * 4);
            int gy = pos >> 1, hf = pos & 1;
            sq[gy * 49 + c * 16 + pr * 2 + hf] = pack4(v, s);
        }
        __syncthreads();
        const int m0 = b * 784 + gx * 28;
        int* dst = (int*)g_xq + (size_t)m0 * 48;
        for (int i = t; i < 1344; i += 256) {
            int gy = i / 48, kw = i - gy * 48;
            dst[i] = sq[gy * 49 + kw];
        }
    } else {
        const int idx = (blockIdx.x - 1792) * 256 + t;   // < 36864
        const float s = fmaxf(__uint_as_float(g_amax_w), 1e-8f) / 127.f;
        ((int*)g_wq)[idx] = pack4(((const float4*)w)[idx], s);
    }
}

// ---------------- IMMA helpers ----------------
__device__ __forceinline__ void ldsm4(uint32_t& r0, uint32_t& r1, uint32_t& r2, uint32_t& r3,
                                      uint32_t addr) {
    asm volatile("ldmatrix.sync.aligned.m8n8.x4.shared.b16 {%0,%1,%2,%3}, [%4];"
                 : "=r"(r0), "=r"(r1), "=r"(r2), "=r"(r3) : "r"(addr));
}
__device__ __forceinline__ void imma(int* c, uint32_t a0, uint32_t a1, uint32_t a2, uint32_t a3,
                                     uint32_t b0, uint32_t b1) {
    asm volatile(
        "mma.sync.aligned.m16n8k32.row.col.s32.s8.s8.s32 "
        "{%0,%1,%2,%3}, {%4,%5,%6,%7}, {%8,%9}, {%0,%1,%2,%3};"
        : "+r"(c[0]), "+r"(c[1]), "+r"(c[2]), "+r"(c[3])
        : "r"(a0), "r"(a1), "r"(a2), "r"(a3), "r"(b0), "r"(b1));
}

#define A_STRIDE 208           // 192 data + 16 pad
#define SA_BYTES (64 * A_STRIDE)
#define SB_BYTES (128 * A_STRIDE)

// Warp-specialized GEMM CTA: tile 64(M) x 128(N).
//   warps 0-3: IMMA (tensor pipe) on cols [0,64): 2x2 warp grid of 32x32 tiles
//   warps 4-7: dp4a (alu pipe)   on cols [64,128): 128 thr, 4x8 per thread
__global__ void __launch_bounds__(256) k_gemm(const float* __restrict__ bias,
                                              float* __restrict__ out) {
    __shared__ __align__(16) char smem[SA_BYTES + SB_BYTES];
    const int t = threadIdx.x;
    const int m0 = blockIdx.x * 64;
    const int n0 = blockIdx.y * 128;

    // cooperative tile load (all 8 warps)
    {
        const int4* gA = g_xq + (size_t)m0 * 12;
        #pragma unroll
        for (int i = t; i < 64 * 12; i += 256) {
            int row = i / 12, kv = i - row * 12;
            *(int4*)(smem + row * A_STRIDE + kv * 16) = gA[i];
        }
        const int4* gB = g_wq + (size_t)n0 * 12;
        #pragma unroll
        for (int i = t; i < 128 * 12; i += 256) {
            int row = i / 12, kv = i - row * 12;
            *(int4*)(smem + SA_BYTES + row * A_STRIDE + kv * 16) = gB[i];
        }
    }
    __syncthreads();

    const float sx = fmaxf(__uint_as_float(g_amax_x), 1e-8f) / 127.f;
    const float sw = fmaxf(__uint_as_float(g_amax_w), 1e-8f) / 127.f;
    const float sc = sx * sw;

    const int warp = t >> 5, lane = t & 31;

    if (warp < 4) {
        // ---------------- IMMA half: cols [0,64) ----------------
        const int wm = warp >> 1, wn = warp & 1;
        const int quad = lane >> 3, li = lane & 7;
        const uint32_t sbase = (uint32_t)__cvta_generic_to_shared(smem);
        const int rsel = ((quad & 1) << 3) + li;
        const int osel = (quad >> 1) << 4;
        uint32_t aAddr0 = sbase + (wm * 32 + rsel) * A_STRIDE + osel;
        uint32_t aAddr1 = aAddr0 + 16 * A_STRIDE;
        uint32_t bAddr0 = sbase + SA_BYTES + (wn * 32 + rsel) * A_STRIDE + osel;
        uint32_t bAddr1 = bAddr0 + 16 * A_STRIDE;

        int acc[2][4][4];
        #pragma unroll
        for (int mi = 0; mi < 2; mi++)
            #pragma unroll
            for (int f = 0; f < 4; f++)
                #pragma unroll
                for (int j = 0; j < 4; j++) acc[mi][f][j] = 0;

        #pragma unroll
        for (int kf = 0; kf < 6; kf++) {
            const uint32_t ko = kf * 32;
            uint32_t a0[4], a1[4], p0[4], p1[4];
            ldsm4(a0[0], a0[1], a0[2], a0[3], aAddr0 + ko);
            ldsm4(a1[0], a1[1], a1[2], a1[3], aAddr1 + ko);
            ldsm4(p0[0], p0[1], p0[2], p0[3], bAddr0 + ko);
            ldsm4(p1[0], p1[1], p1[2], p1[3], bAddr1 + ko);
            imma(acc[0][0], a0[0], a0[1], a0[2], a0[3], p0[0], p0[2]);
            imma(acc[0][1], a0[0], a0[1], a0[2], a0[3], p0[1], p0[3]);
            imma(acc[0][2], a0[0], a0[1], a0[2], a0[3], p1[0], p1[2]);
            imma(acc[0][3], a0[0], a0[1], a0[2], a0[3], p1[1], p1[3]);
            imma(acc[1][0], a1[0], a1[1], a1[2], a1[3], p0[0], p0[2]);
            imma(acc[1][1], a1[0], a1[1], a1[2], a1[3], p0[1], p0[3]);
            imma(acc[1][2], a1[0], a1[1], a1[2], a1[3], p1[0], p1[2]);
            imma(acc[1][3], a1[0], a1[1], a1[2], a1[3], p1[1], p1[3]);
        }

        const int rr = lane >> 2, cp = lane & 3;
        #pragma unroll
        for (int f = 0; f < 4; f++) {
            const int col = n0 + wn * 32 + f * 8 + cp * 2;
            const float2 bv = *(const float2*)(bias + col);
            #pragma unroll
            for (int mi = 0; mi < 2; mi++) {
                const int row0 = m0 + wm * 32 + mi * 16 + rr;
                float2 v0, v1;
                v0.x = (float)acc[mi][f][0] * sc + bv.x;
                v0.y = (float)acc[mi][f][1] * sc + bv.y;
                v1.x = (float)acc[mi][f][2] * sc + bv.x;
                v1.y = (float)acc[mi][f][3] * sc + bv.y;
                *(float2*)(out + (size_t)row0 * NN + col)       = v0;
                *(float2*)(out + (size_t)(row0 + 8) * NN + col) = v1;
            }
        }
    } else {
        // ---------------- dp4a half: cols [64,128) ----------------
        const int t2 = t & 127;
        const int tx = t2 & 7, ty = t2 >> 3;       // 8 col-groups x 16 row-groups
        const int rowb = ty * 4;

        int acc[4][8];
        #pragma unroll
        for (int r = 0; r < 4; r++)
            #pragma unroll
            for (int j = 0; j < 8; j++) acc[r][j] = 0;

        #pragma unroll
        for (int k4 = 0; k4 < 12; k4++) {
            int4 a0 = *(const int4*)(smem + (rowb + 0) * A_STRIDE + k4 * 16);
            int4 a1 = *(const int4*)(smem + (rowb + 1) * A_STRIDE + k4 * 16);
            int4 a2 = *(const int4*)(smem + (rowb + 2) * A_STRIDE + k4 * 16);
            int4 a3 = *(const int4*)(smem + (rowb + 3) * A_STRIDE + k4 * 16);
            int4 bv[8];
            #pragma unroll
            for (int j = 0; j < 8; j++)
                bv[j] = *(const int4*)(smem + SA_BYTES + (64 + tx * 8 + j) * A_STRIDE + k4 * 16);
            const int* ap0 = (const int*)&a0;
            const int* ap1 = (const int*)&a1;
            const int* ap2 = (const int*)&a2;
            const int* ap3 = (const int*)&a3;
            #pragma unroll
            for (int kk = 0; kk < 4; kk++) {
                int aw[4] = {ap0[kk], ap1[kk], ap2[kk], ap3[kk]};
                #pragma unroll
                for (int r = 0; r < 4; r++)
                    #pragma unroll
                    for (int j = 0; j < 8; j++)
                        acc[r][j] = __dp4a(aw[r], ((const int*)&bv[j])[kk], acc[r][j]);
            }
        }

        const int col0 = n0 + 64 + tx * 8;
        const float4 bLo = *(const float4*)(bias + col0);
        const float4 bHi = *(const float4*)(bias + col0 + 4);
        #pragma unroll
        for (int r = 0; r < 4; r++) {
            float* o = out + (size_t)(m0 + rowb + r) * NN + col0;
            float4 v0, v1;
            v0.x = (float)acc[r][0] * sc + bLo.x;
            v0.y = (float)acc[r][1] * sc + bLo.y;
            v0.z = (float)acc[r][2] * sc + bLo.z;
            v0.w = (float)acc[r][3] * sc + bLo.w;
            v1.x = (float)acc[r][4] * sc + bHi.x;
            v1.y = (float)acc[r][5] * sc + bHi.y;
            v1.z = (float)acc[r][6] * sc + bHi.z;
            v1.w = (float)acc[r][7] * sc + bHi.w;
            *(float4*)o       = v0;
            *(float4*)(o + 4) = v1;
        }
    }
}

// ---------------- launch ----------------
extern "C" void kernel_launch(void* const* d_in, const int* in_sizes, int n_in,
                              void* d_out, int out_size) {
    const float* x = (const float*)d_in[0];   // [64,3,224,224]
    const float* w = (const float*)d_in[1];   // [768,3,8,8]
    const float* b = (const float*)d_in[2];   // [768]
    float* out = (float*)d_out;               // [64,784,768] fp32

    k_init<<<1, 1>>>();
    dim3 agrid(1024, 2);
    k_absmax<<<agrid, 256>>>((const float4*)x, (BB * 3 * 224 * 224) / 4,
                             (const float4*)w, (NN * KK) / 4);
    k_quant<<<1792 + 144, 256>>>(x, w);
    dim3 grid(MM / 64, NN / 128);
    k_gemm<<<grid, 256>>>(b, out);
}

// round 8
// speedup vs baseline: 2.0540x; 2.0540x over previous
#include <cuda_runtime.h>
#include <cstdint>

// Problem constants
#define BB   64
#define MM   50176         // B*28*28
#define NN   768
#define KK   192
#define KWRD 48            // K in int words (4 int8 each)

// ---------------- device scratch ----------------
__device__ unsigned g_amax_x, g_amax_w;
__device__ int4 g_xq[MM * KWRD / 4];    // [M][48] words: A, row-major k
__device__ int4 g_wq[NN * KWRD / 4];    // [N][48] words: B, n-major (natural w layout)

// ---------------- small kernels ----------------
__global__ void k_init() { g_amax_x = 0u; g_amax_w = 0u; }

__global__ void k_absmax(const float4* __restrict__ px, int nx4,
                         const float4* __restrict__ pw, int nw4) {
    const float4* p = blockIdx.y ? pw : px;
    const int n4 = blockIdx.y ? nw4 : nx4;
    float m = 0.f;
    for (int i = blockIdx.x * blockDim.x + threadIdx.x; i < n4; i += gridDim.x * blockDim.x) {
        float4 v = p[i];
        m = fmaxf(m, fmaxf(fmaxf(fabsf(v.x), fabsf(v.y)), fmaxf(fabsf(v.z), fabsf(v.w))));
    }
    #pragma unroll
    for (int o = 16; o; o >>= 1) m = fmaxf(m, __shfl_xor_sync(0xffffffffu, m, o));
    __shared__ float sm[8];
    if ((threadIdx.x & 31) == 0) sm[threadIdx.x >> 5] = m;
    __syncthreads();
    if (threadIdx.x < 32) {
        m = (threadIdx.x < 8) ? sm[threadIdx.x] : 0.f;
        #pragma unroll
        for (int o = 4; o; o >>= 1) m = fmaxf(m, __shfl_xor_sync(0xffffffffu, m, o));
        if (threadIdx.x == 0)
            atomicMax(blockIdx.y ? &g_amax_w : &g_amax_x, __float_as_uint(m));
    }
}

__device__ __forceinline__ int quant1(float v, float s) {
    float t = v / s;
    t = fminf(fmaxf(t, -127.f), 127.f);
    return __float2int_rn(t);
}
__device__ __forceinline__ int pack4(float4 v, float s) {
    int i0 = quant1(v.x, s), i1 = quant1(v.y, s), i2 = quant1(v.z, s), i3 = quant1(v.w, s);
    return (i0 & 0xff) | ((i1 & 0xff) << 8) | ((i2 & 0xff) << 16) | ((i3 & 0xff) << 24);
}

// Fused quantization: blocks [0,1792) handle x slabs, [1792,1936) handle w.
__global__ void __launch_bounds__(256) k_quant(const float* __restrict__ x,
                                               const float* __restrict__ w) {
    const int t = threadIdx.x;
    if (blockIdx.x < 1792) {
        __shared__ int sq[28 * 49];
        const int b = blockIdx.x / 28, gx = blockIdx.x % 28;
        const float s = fmaxf(__uint_as_float(g_amax_x), 1e-8f) / 127.f;
        for (int i = t; i < 1344; i += 256) {
            int row = i / 56, pos = i - row * 56;        // row = c*8+pr
            int c = row >> 3, pr = row & 7;
            float4 v = *(const float4*)(x + (((b * 3 + c) * 224 + gx * 8 + pr) * 224) + pos * 4);
            int gy = pos >> 1, hf = pos & 1;
            sq[gy * 49 + c * 16 + pr * 2 + hf] = pack4(v, s);
        }
        __syncthreads();
        const int m0 = b * 784 + gx * 28;
        int* dst = (int*)g_xq + (size_t)m0 * 48;
        for (int i = t; i < 1344; i += 256) {
            int gy = i / 48, kw = i - gy * 48;
            dst[i] = sq[gy * 49 + kw];
        }
    } else {
        const int idx = (blockIdx.x - 1792) * 256 + t;   // < 36864
        const float s = fmaxf(__uint_as_float(g_amax_w), 1e-8f) / 127.f;
        ((int*)g_wq)[idx] = pack4(((const float4*)w)[idx], s);
    }
}

// ---------------- IMMA helpers ----------------
__device__ __forceinline__ void ldsm4(uint32_t& r0, uint32_t& r1, uint32_t& r2, uint32_t& r3,
                                      uint32_t addr) {
    asm volatile("ldmatrix.sync.aligned.m8n8.x4.shared.b16 {%0,%1,%2,%3}, [%4];"
                 : "=r"(r0), "=r"(r1), "=r"(r2), "=r"(r3) : "r"(addr));
}
__device__ __forceinline__ void imma(int* c, uint32_t a0, uint32_t a1, uint32_t a2, uint32_t a3,
                                     uint32_t b0, uint32_t b1) {
    asm volatile(
        "mma.sync.aligned.m16n8k32.row.col.s32.s8.s8.s32 "
        "{%0,%1,%2,%3}, {%4,%5,%6,%7}, {%8,%9}, {%0,%1,%2,%3};"
        : "+r"(c[0]), "+r"(c[1]), "+r"(c[2]), "+r"(c[3])
        : "r"(a0), "r"(a1), "r"(a2), "r"(a3), "r"(b0), "r"(b1));
}

#define A_STRIDE 208           // 192 data + 16 pad
#define SA_BYTES (64 * A_STRIDE)
#define SB_BYTES (128 * A_STRIDE)

// CTA 64(M) x 128(N), 256 thr = 8 warps of 32x32. Full K=192 resident.
// occ target 3 CTAs/SM to hide prologue/epilogue behind peer CTAs' MMA phases.
__global__ void __launch_bounds__(256, 3) k_gemm(const float* __restrict__ bias,
                                                 float* __restrict__ out) {
    __shared__ __align__(16) char smem[SA_BYTES + SB_BYTES];
    const int t = threadIdx.x;
    const int m0 = blockIdx.x * 64;
    const int n0 = blockIdx.y * 128;

    // load tiles (linear, coalesced)
    {
        const int4* gA = g_xq + (size_t)m0 * 12;
        #pragma unroll
        for (int i = t; i < 64 * 12; i += 256) {
            int row = i / 12, kv = i - row * 12;
            *(int4*)(smem + row * A_STRIDE + kv * 16) = gA[i];
        }
        const int4* gB = g_wq + (size_t)n0 * 12;
        #pragma unroll
        for (int i = t; i < 128 * 12; i += 256) {
            int row = i / 12, kv = i - row * 12;
            *(int4*)(smem + SA_BYTES + row * A_STRIDE + kv * 16) = gB[i];
        }
    }
    __syncthreads();

    const int warp = t >> 5, lane = t & 31;
    const int wm = warp >> 2, wn = warp & 3;       // warp tile: rows wm*32, cols wn*32
    const int quad = lane >> 3, li = lane & 7;
    const uint32_t sbase = (uint32_t)__cvta_generic_to_shared(smem);

    const int rsel = ((quad & 1) << 3) + li;
    const int osel = (quad >> 1) << 4;
    uint32_t aAddr0 = sbase + (wm * 32 + rsel) * A_STRIDE + osel;
    uint32_t aAddr1 = aAddr0 + 16 * A_STRIDE;
    uint32_t bAddr0 = sbase + SA_BYTES + (wn * 32 + rsel) * A_STRIDE + osel;
    uint32_t bAddr1 = bAddr0 + 16 * A_STRIDE;

    int acc[2][4][4];
    #pragma unroll
    for (int mi = 0; mi < 2; mi++)
        #pragma unroll
        for (int f = 0; f < 4; f++)
            #pragma unroll
            for (int j = 0; j < 4; j++) acc[mi][f][j] = 0;

    #pragma unroll
    for (int kf = 0; kf < 6; kf++) {
        const uint32_t ko = kf * 32;
        uint32_t a0[4], a1[4], p0[4], p1[4];
        ldsm4(a0[0], a0[1], a0[2], a0[3], aAddr0 + ko);
        ldsm4(a1[0], a1[1], a1[2], a1[3], aAddr1 + ko);
        ldsm4(p0[0], p0[1], p0[2], p0[3], bAddr0 + ko);   // n-frags 0,1
        ldsm4(p1[0], p1[1], p1[2], p1[3], bAddr1 + ko);   // n-frags 2,3
        imma(acc[0][0], a0[0], a0[1], a0[2], a0[3], p0[0], p0[2]);
        imma(acc[0][1], a0[0], a0[1], a0[2], a0[3], p0[1], p0[3]);
        imma(acc[0][2], a0[0], a0[1], a0[2], a0[3], p1[0], p1[2]);
        imma(acc[0][3], a0[0], a0[1], a0[2], a0[3], p1[1], p1[3]);
        imma(acc[1][0], a1[0], a1[1], a1[2], a1[3], p0[0], p0[2]);
        imma(acc[1][1], a1[0], a1[1], a1[2], a1[3], p0[1], p0[3]);
        imma(acc[1][2], a1[0], a1[1], a1[2], a1[3], p1[0], p1[2]);
        imma(acc[1][3], a1[0], a1[1], a1[2], a1[3], p1[1], p1[3]);
    }

    const float sx = fmaxf(__uint_as_float(g_amax_x), 1e-8f) / 127.f;
    const float sw = fmaxf(__uint_as_float(g_amax_w), 1e-8f) / 127.f;
    const float sc = sx * sw;

    const int r = lane >> 2, cp = lane & 3;
    #pragma unroll
    for (int f = 0; f < 4; f++) {
        const int col = n0 + wn * 32 + f * 8 + cp * 2;
        const float2 bv = *(const float2*)(bias + col);
        #pragma unroll
        for (int mi = 0; mi < 2; mi++) {
            const int row0 = m0 + wm * 32 + mi * 16 + r;
            float2 v0, v1;
            v0.x = (float)acc[mi][f][0] * sc + bv.x;
            v0.y = (float)acc[mi][f][1] * sc + bv.y;
            v1.x = (float)acc[mi][f][2] * sc + bv.x;
            v1.y = (float)acc[mi][f][3] * sc + bv.y;
            *(float2*)(out + (size_t)row0 * NN + col)       = v0;
            *(float2*)(out + (size_t)(row0 + 8) * NN + col) = v1;
        }
    }
}

// ---------------- launch ----------------
extern "C" void kernel_launch(void* const* d_in, const int* in_sizes, int n_in,
                              void* d_out, int out_size) {
    const float* x = (const float*)d_in[0];   // [64,3,224,224]
    const float* w = (const float*)d_in[1];   // [768,3,8,8]
    const float* b = (const float*)d_in[2];   // [768]
    float* out = (float*)d_out;               // [64,784,768] fp32

    k_init<<<1, 1>>>();
    dim3 agrid(1024, 2);
    k_absmax<<<agrid, 256>>>((const float4*)x, (BB * 3 * 224 * 224) / 4,
                             (const float4*)w, (NN * KK) / 4);
    k_quant<<<1792 + 144, 256>>>(x, w);
    dim3 grid(MM / 64, NN / 128);
    k_gemm<<<grid, 256>>>(b, out);
}